// round 16
// baseline (speedup 1.0000x reference)
#include <cuda_runtime.h>
#include <math.h>

#define NN 50000
#define EE 800000
#define IND 256
#define HH 4
#define CC 64
#define HC 256   // H*C
#define LAT 32
#define EDIM 3

typedef unsigned long long ull;

// ---------------- scratch (device globals; no allocation allowed) ----------------
// g_deg and g_loop are SELF-CLEANING across calls:
//   g_deg:  edge_accum raises 0->deg, scatter counts back down to 0.
//   g_loop: accumulated by edge_accum, scaled by scan_add2, zeroed by the
//           layer-1 gat_agg after its final read.
__device__ int    g_deg[NN];
__device__ int    g_off[NN + 1];
__device__ float4 g_erec[EE];       // {src_as_float, ea0, ea1, ea2} in CSR order
__device__ int    g_bsum[64];
__device__ float  g_loop[NN * EDIM];
__device__ float  g_xl[NN * HC];
__device__ float  g_xr[NN * HC];
__device__ float  g_h1[NN * CC];
__device__ float  g_h2[NN * CC];

// ---------------- packed f32x2 helpers ----------------
__device__ __forceinline__ ull pk2(float lo, float hi) {
    ull r; asm("mov.b64 %0, {%1,%2};" : "=l"(r) : "f"(lo), "f"(hi)); return r;
}
__device__ __forceinline__ ull bc2(float x) { return pk2(x, x); }
__device__ __forceinline__ ull fma2(ull a, ull b, ull c) {
    ull d; asm("fma.rn.f32x2 %0, %1, %2, %3;" : "=l"(d) : "l"(a), "l"(b), "l"(c)); return d;
}
__device__ __forceinline__ ull add2(ull a, ull b) {
    ull d; asm("add.rn.f32x2 %0, %1, %2;" : "=l"(d) : "l"(a), "l"(b)); return d;
}
__device__ __forceinline__ ull mul2(ull a, ull b) {
    ull d; asm("mul.rn.f32x2 %0, %1, %2;" : "=l"(d) : "l"(a), "l"(b)); return d;
}
__device__ __forceinline__ void unpk2(ull v, float& lo, float& hi) {
    asm("mov.b64 {%0,%1}, %2;" : "=f"(lo), "=f"(hi) : "l"(v));
}

// ---------------- CSR build ----------------
__global__ void edge_accum_kernel(const int* __restrict__ dst,
                                  const float* __restrict__ ea, int e) {
    int i = blockIdx.x * blockDim.x + threadIdx.x;
    if (i < e) {
        int d = dst[i];
        atomicAdd(&g_deg[d], 1);
        atomicAdd(&g_loop[d * 3 + 0], ea[i * 3 + 0]);
        atomicAdd(&g_loop[d * 3 + 1], ea[i * 3 + 1]);
        atomicAdd(&g_loop[d * 3 + 2], ea[i * 3 + 2]);
    }
}

__global__ void scan_block_kernel(int n) {
    __shared__ int tmp[1024];
    int tid = threadIdx.x;
    int i = blockIdx.x * 1024 + tid;
    int v = (i < n) ? g_deg[i] : 0;
    tmp[tid] = v;
    __syncthreads();
    for (int d = 1; d < 1024; d <<= 1) {
        int t = (tid >= d) ? tmp[tid - d] : 0;
        __syncthreads();
        tmp[tid] += t;
        __syncthreads();
    }
    if (i < n) g_off[i + 1] = tmp[tid];
    if (tid == 1023) g_bsum[blockIdx.x] = tmp[tid];
    if (i == 0) g_off[0] = 0;
}

// merged: block-prefix from g_bsum (computed in-kernel) + loop_attr mean.
// g_deg stays intact here; scatter consumes it as a countdown.
__global__ void scan_add2_kernel(int n) {
    __shared__ int pre;
    if (threadIdx.x == 0) {
        int s = 0;
        for (int b = 0; b < (int)blockIdx.x; b++) s += g_bsum[b];
        pre = s;
    }
    __syncthreads();
    int i = blockIdx.x * 1024 + threadIdx.x;
    if (i < n) {
        g_off[i + 1] += pre;
        float inv = 1.0f / (float)max(g_deg[i], 1);
        g_loop[i * 3 + 0] *= inv;
        g_loop[i * 3 + 1] *= inv;
        g_loop[i * 3 + 2] *= inv;
    }
}

// writes packed edge records {src, ea0, ea1, ea2} into CSR slots.
// Uses g_deg as a countdown counter; leaves g_deg == 0 (self-cleaning).
__global__ void scatter_kernel(const int* __restrict__ dst,
                               const int* __restrict__ src,
                               const float* __restrict__ ea, int e) {
    int i = blockIdx.x * blockDim.x + threadIdx.x;
    if (i < e) {
        int d = dst[i];
        int p = g_off[d] + atomicSub(&g_deg[d], 1) - 1;
        g_erec[p] = make_float4(__int_as_float(src[i]),
                                ea[i * 3 + 0], ea[i * 3 + 1], ea[i * 3 + 2]);
    }
}

// ---------------- TF32 tensor-core GEMM (R12 config: best measured) ----------
#define AS_STRIDE 36
#define BS_STRIDE 136
#define AS_STAGE (128 * AS_STRIDE)
#define BS_STAGE (32 * BS_STRIDE)
#define NSTAGE 3
#define GEMM_SMEM_BYTES ((NSTAGE * AS_STAGE + NSTAGE * BS_STAGE) * 4)

__device__ __forceinline__ void cp16(unsigned saddr, const float* g, unsigned srcsz) {
    asm volatile("cp.async.cg.shared.global [%0], [%1], 16, %2;"
                 :: "r"(saddr), "l"(g), "r"(srcsz));
}

__global__ __launch_bounds__(256) void gemm_tf32_dual(
    const float* __restrict__ A,
    const float* __restrict__ Bl, const float* __restrict__ Br,
    const float* __restrict__ bl, const float* __restrict__ br,
    float* __restrict__ Cl, float* __restrict__ Cr,
    int M, int K)
{
    extern __shared__ float sm[];
    float* Asm = sm;
    float* Bsm = sm + NSTAGE * AS_STAGE;

    const int tid  = threadIdx.x;
    const int lane = tid & 31;
    const int warp = tid >> 5;
    const int g = lane >> 2;
    const int q = lane & 3;

    const int m_warp = (warp & 1) * 64;
    const int n_warp = (warp >> 1) * 32;

    const int row0 = blockIdx.y * 128;
    const int col0 = blockIdx.x * 128;
    const int half = (col0 >= 256);
    const float* Bp = half ? Br : Bl;
    const float* biasp = half ? br : bl;
    float* Cp = half ? Cr : Cl;
    const int bcol0 = col0 - half * 256;

    const int ar = tid >> 1;
    const int brow = tid >> 3;
    const int bc4 = (tid & 7) * 4;

    const unsigned asm_base = (unsigned)__cvta_generic_to_shared(Asm);
    const unsigned bsm_base = (unsigned)__cvta_generic_to_shared(Bsm);

    float acc[4][4][4] = {};
    const int nk = K >> 5;

    auto load_stage = [&](int stg, int k0) {
        const int garow = row0 + ar;
        const int carow = (garow < M) ? garow : (M - 1);
        const unsigned asz = (garow < M) ? 16u : 0u;
        const float* gA = A + (long)carow * K + k0;
        unsigned sA = asm_base + (stg * AS_STAGE + ar * AS_STRIDE) * 4;
        int cbase = (tid & 1) * 16;
        cp16(sA + (cbase + 0) * 4, gA + cbase + 0, asz);
        cp16(sA + (cbase + 4) * 4, gA + cbase + 4, asz);
        cp16(sA + (cbase + 8) * 4, gA + cbase + 8, asz);
        cp16(sA + (cbase + 12) * 4, gA + cbase + 12, asz);
        const float* gB = Bp + (long)(k0 + brow) * 256 + bcol0 + bc4;
        unsigned sB = bsm_base + (stg * BS_STAGE + brow * BS_STRIDE + bc4) * 4;
        cp16(sB, gB, 16u);
        cp16(sB + 32 * 4, gB + 32, 16u);
        cp16(sB + 64 * 4, gB + 64, 16u);
        cp16(sB + 96 * 4, gB + 96, 16u);
    };

    load_stage(0, 0);
    asm volatile("cp.async.commit_group;");
    load_stage(1, 32);
    asm volatile("cp.async.commit_group;");

    int stg = 0;
    int stg2 = 2;
    for (int kt = 0; kt < nk; kt++) {
        if (kt == nk - 1)
            asm volatile("cp.async.wait_group 0;");
        else
            asm volatile("cp.async.wait_group 1;");
        __syncthreads();

        if (kt + 2 < nk) {
            load_stage(stg2, (kt + 2) * 32);
            asm volatile("cp.async.commit_group;");
        }

        const float* As = Asm + stg * AS_STAGE;
        const float* Bs = Bsm + stg * BS_STAGE;

        #pragma unroll
        for (int kk = 0; kk < 32; kk += 8) {
            unsigned a[4][4], b[4][2];
            #pragma unroll
            for (int i = 0; i < 4; i++) {
                int r = m_warp + i * 16 + g;
                a[i][0] = __float_as_uint(As[r * AS_STRIDE + kk + q]) + 0x1000u;
                a[i][1] = __float_as_uint(As[(r + 8) * AS_STRIDE + kk + q]) + 0x1000u;
                a[i][2] = __float_as_uint(As[r * AS_STRIDE + kk + q + 4]) + 0x1000u;
                a[i][3] = __float_as_uint(As[(r + 8) * AS_STRIDE + kk + q + 4]) + 0x1000u;
            }
            #pragma unroll
            for (int j = 0; j < 4; j++) {
                int c = n_warp + j * 8 + g;
                b[j][0] = __float_as_uint(Bs[(kk + q) * BS_STRIDE + c]) + 0x1000u;
                b[j][1] = __float_as_uint(Bs[(kk + q + 4) * BS_STRIDE + c]) + 0x1000u;
            }
            #pragma unroll
            for (int i = 0; i < 4; i++)
                #pragma unroll
                for (int j = 0; j < 4; j++) {
                    asm volatile(
                        "mma.sync.aligned.m16n8k8.row.col.f32.tf32.tf32.f32 "
                        "{%0,%1,%2,%3}, {%4,%5,%6,%7}, {%8,%9}, {%0,%1,%2,%3};"
                        : "+f"(acc[i][j][0]), "+f"(acc[i][j][1]),
                          "+f"(acc[i][j][2]), "+f"(acc[i][j][3])
                        : "r"(a[i][0]), "r"(a[i][1]), "r"(a[i][2]), "r"(a[i][3]),
                          "r"(b[j][0]), "r"(b[j][1]));
                }
        }
        stg = (stg == NSTAGE - 1) ? 0 : stg + 1;
        stg2 = (stg2 == NSTAGE - 1) ? 0 : stg2 + 1;
    }

    #pragma unroll
    for (int i = 0; i < 4; i++) {
        int r0 = row0 + m_warp + i * 16 + g;
        #pragma unroll
        for (int j = 0; j < 4; j++) {
            int cl = bcol0 + n_warp + j * 8 + 2 * q;
            float b0 = biasp[cl], b1 = biasp[cl + 1];
            if (r0 < M) {
                Cp[(long)r0 * 256 + cl]     = acc[i][j][0] + b0;
                Cp[(long)r0 * 256 + cl + 1] = acc[i][j][1] + b1;
            }
            if (r0 + 8 < M) {
                Cp[(long)(r0 + 8) * 256 + cl]     = acc[i][j][2] + b0;
                Cp[(long)(r0 + 8) * 256 + cl + 1] = acc[i][j][3] + b1;
            }
        }
    }
}

// ---------------- fp32 tiled SGEMM (final projection only) ----------------
__global__ void sgemm_bias(const float* __restrict__ A, const float* __restrict__ B,
                           const float* __restrict__ bias, float* __restrict__ C,
                           int M, int K, int Nc) {
    __shared__ float As[16][64];
    __shared__ float Bs[16][64 + 4];
    int tid = threadIdx.x;
    int tx = tid & 15, ty = tid >> 4;
    int row0 = blockIdx.y * 64, col0 = blockIdx.x * 64;
    float acc[4][4] = {};
    for (int k0 = 0; k0 < K; k0 += 16) {
        #pragma unroll
        for (int i = tid; i < 64 * 16; i += 256) {
            int m = i >> 4, k = i & 15;
            int r = row0 + m;
            As[k][m] = (r < M) ? A[(long)r * K + k0 + k] : 0.0f;
        }
        #pragma unroll
        for (int i = tid; i < 16 * 64; i += 256) {
            int k = i >> 6, c = i & 63;
            int cc = col0 + c;
            Bs[k][c] = (cc < Nc) ? B[(long)(k0 + k) * Nc + cc] : 0.0f;
        }
        __syncthreads();
        #pragma unroll
        for (int k = 0; k < 16; k++) {
            float a[4], b[4];
            #pragma unroll
            for (int i = 0; i < 4; i++) a[i] = As[k][ty * 4 + i];
            #pragma unroll
            for (int j = 0; j < 4; j++) b[j] = Bs[k][tx * 4 + j];
            #pragma unroll
            for (int i = 0; i < 4; i++)
                #pragma unroll
                for (int j = 0; j < 4; j++)
                    acc[i][j] += a[i] * b[j];
        }
        __syncthreads();
    }
    #pragma unroll
    for (int i = 0; i < 4; i++) {
        int r = row0 + ty * 4 + i;
        if (r >= M) continue;
        #pragma unroll
        for (int j = 0; j < 4; j++) {
            int c = col0 + tx * 4 + j;
            if (c < Nc) C[(long)r * Nc + c] = acc[i][j] + bias[c];
        }
    }
}

// ---------------- fused GATv2 attention + aggregation ----------------
#define ABSMASK 0x7FFFFFFF7FFFFFFFULL

__global__ __launch_bounds__(256) void gat_agg(
        const float* __restrict__ xl, const float* __restrict__ xr,
        const float* __restrict__ We, const float* __restrict__ att,
        const float* __restrict__ bias, float* __restrict__ out,
        int n, int clear_loop) {
    int warp = (blockIdx.x * blockDim.x + threadIdx.x) >> 5;
    int lane = threadIdx.x & 31;
    if (warp >= n) return;
    const int node = warp;
    const int base = ((lane >> 3) << 6) | ((lane & 7) << 3);
    const int b4 = base >> 2;

    ull we0[4], we1[4], we2[4], attv[4], xrv[4];
    {
        const float4* We4 = (const float4*)We;
        const float4* at4 = (const float4*)att;
        const float4* xr4 = (const float4*)(xr + (long)node * HC);
        *(float4*)&we0[0] = We4[b4];        *(float4*)&we0[2] = We4[b4 + 1];
        *(float4*)&we1[0] = We4[64 + b4];   *(float4*)&we1[2] = We4[64 + b4 + 1];
        *(float4*)&we2[0] = We4[128 + b4];  *(float4*)&we2[2] = We4[128 + b4 + 1];
        *(float4*)&attv[0] = at4[b4];       *(float4*)&attv[2] = at4[b4 + 1];
        *(float4*)&xrv[0] = xr4[b4];        *(float4*)&xrv[2] = xr4[b4 + 1];
    }
    const ull C06 = 0x3F19999A3F19999AULL;   // {0.6f, 0.6f}
    const ull C04 = 0x3ECCCCCD3ECCCCCDULL;   // {0.4f, 0.4f}

    const int o0 = g_off[node];
    const int deg = g_off[node + 1] - o0;

    auto fetch = [&](int pos, int& sn, float& e0, float& e1, float& e2) {
        if (pos < deg) {
            float4 rec = __ldg(&g_erec[o0 + pos]);
            sn = __float_as_int(rec.x);
            e0 = rec.y; e1 = rec.z; e2 = rec.w;
        } else { sn = node; e0 = 0.f; e1 = 0.f; e2 = 0.f; }
    };

    auto logit = [&](const ull* cx, float e0, float e1, float e2) -> float {
        ull ea0 = bc2(e0), ea1 = bc2(e1), ea2 = bc2(e2);
        ull p2 = 0;
        #pragma unroll
        for (int j = 0; j < 4; j++) {
            ull bse = fma2(ea2, we2[j], fma2(ea1, we1[j], fma2(ea0, we0[j], xrv[j])));
            ull t = add2(cx[j], bse);
            ull l = fma2(C04, t & ABSMASK, mul2(C06, t));
            p2 = fma2(l, attv[j], p2);
        }
        float lo, hi;
        unpk2(p2, lo, hi);
        float p = lo + hi;
        p += __shfl_xor_sync(0xffffffffu, p, 1);
        p += __shfl_xor_sync(0xffffffffu, p, 2);
        p += __shfl_xor_sync(0xffffffffu, p, 4);
        return p;
    };

    // ---- state A seeded with the self-loop, state B empty ----
    ull accA[4], accB[4];
    float mA, sA, mB = -1e30f, sB = 0.f;
    {
        ull xvS[4];
        const float4* xp = (const float4*)(xl + (long)node * HC);
        *(float4*)&xvS[0] = xp[b4];
        *(float4*)&xvS[2] = xp[b4 + 1];
        float l0 = g_loop[node * 3 + 0];
        float l1 = g_loop[node * 3 + 1];
        float l2 = g_loop[node * 3 + 2];
        if (clear_loop && lane == 0) {   // last consumer resets g_loop to 0
            g_loop[node * 3 + 0] = 0.f;
            g_loop[node * 3 + 1] = 0.f;
            g_loop[node * 3 + 2] = 0.f;
        }
        mA = logit(xvS, l0, l1, l2);
        sA = 1.f;
        #pragma unroll
        for (int j = 0; j < 4; j++) { accA[j] = xvS[j]; accB[j] = 0; }
    }

    // ---- meta queue: pair 0 (current) + pair 1 (next) ----
    int snA0, snB0, snA1, snB1;
    float a00, a01, a02, b00, b01, b02;
    float a10, a11, a12, b10, b11, b12;
    fetch(0, snA0, a00, a01, a02);
    fetch(1, snB0, b00, b01, b02);
    ull xvA[4], xvB[4];
    {
        const float4* xp = (const float4*)(xl + (long)snA0 * HC);
        *(float4*)&xvA[0] = xp[b4]; *(float4*)&xvA[2] = xp[b4 + 1];
    }
    {
        const float4* xp = (const float4*)(xl + (long)snB0 * HC);
        *(float4*)&xvB[0] = xp[b4]; *(float4*)&xvB[2] = xp[b4 + 1];
    }
    fetch(2, snA1, a10, a11, a12);
    fetch(3, snB1, b10, b11, b12);

    for (int i = 0; i < deg; i += 2) {
        ull cxA[4], cxB[4];
        #pragma unroll
        for (int j = 0; j < 4; j++) { cxA[j] = xvA[j]; cxB[j] = xvB[j]; }
        const float cA0 = a00, cA1 = a01, cA2 = a02;
        const float cB0 = b00, cB1 = b01, cB2 = b02;
        const bool vB = (i + 1 < deg);

        if (i + 2 < deg) {
            const float4* xp = (const float4*)(xl + (long)snA1 * HC);
            *(float4*)&xvA[0] = xp[b4]; *(float4*)&xvA[2] = xp[b4 + 1];
        }
        if (i + 3 < deg) {
            const float4* xp = (const float4*)(xl + (long)snB1 * HC);
            *(float4*)&xvB[0] = xp[b4]; *(float4*)&xvB[2] = xp[b4 + 1];
        }
        snA0 = snA1; a00 = a10; a01 = a11; a02 = a12;
        snB0 = snB1; b00 = b10; b01 = b11; b02 = b12;
        fetch(i + 4, snA1, a10, a11, a12);
        fetch(i + 5, snB1, b10, b11, b12);

        float pA = logit(cxA, cA0, cA1, cA2);
        float pB = logit(cxB, cB0, cB1, cB2);
        if (!vB) pB = -1e30f;

        float nmA = fmaxf(mA, pA), nmB = fmaxf(mB, pB);
        float scA = __expf(mA - nmA), wA = __expf(pA - nmA);
        float scB = __expf(mB - nmB), wB = __expf(pB - nmB);
        if (!vB) wB = 0.f;
        sA = sA * scA + wA; mA = nmA;
        sB = sB * scB + wB; mB = nmB;
        ull scA2 = bc2(scA), wA2 = bc2(wA);
        ull scB2 = bc2(scB), wB2 = bc2(wB);
        #pragma unroll
        for (int j = 0; j < 4; j++) {
            accA[j] = fma2(wA2, cxA[j], mul2(accA[j], scA2));
            accB[j] = fma2(wB2, cxB[j], mul2(accB[j], scB2));
        }
    }

    // ---- merge states, head mean, bias, relu ----
    float nm = fmaxf(mA, mB);
    float fA = __expf(mA - nm), fB = __expf(mB - nm);
    float inv = 1.f / (sA * fA + sB * fB);
    ull fA2 = bc2(fA * inv), fB2 = bc2(fB * inv);
    float r[8];
    #pragma unroll
    for (int j = 0; j < 4; j++) {
        ull v2 = add2(mul2(accA[j], fA2), mul2(accB[j], fB2));
        float lo, hi;
        unpk2(v2, lo, hi);
        lo += __shfl_xor_sync(0xffffffffu, lo, 8);
        hi += __shfl_xor_sync(0xffffffffu, hi, 8);
        lo += __shfl_xor_sync(0xffffffffu, lo, 16);
        hi += __shfl_xor_sync(0xffffffffu, hi, 16);
        r[2 * j] = lo; r[2 * j + 1] = hi;
    }
    if (lane < 8) {
        float o[8];
        #pragma unroll
        for (int j = 0; j < 8; j++)
            o[j] = fmaxf(0.25f * r[j] + bias[base + j], 0.f);
        float4* op = (float4*)(out + (long)node * CC + base);
        op[0] = make_float4(o[0], o[1], o[2], o[3]);
        op[1] = make_float4(o[4], o[5], o[6], o[7]);
    }
}

// ---------------- launch ----------------
extern "C" void kernel_launch(void* const* d_in, const int* in_sizes, int n_in,
                              void* d_out, int out_size) {
    const float* x          = (const float*)d_in[0];
    const int*   edge_index = (const int*)d_in[1];
    const float* edge_attr  = (const float*)d_in[2];
    const float* Wl0  = (const float*)d_in[3];
    const float* bl0  = (const float*)d_in[4];
    const float* Wr0  = (const float*)d_in[5];
    const float* br0  = (const float*)d_in[6];
    const float* We0  = (const float*)d_in[7];
    const float* att0 = (const float*)d_in[8];
    const float* bias0= (const float*)d_in[9];
    const float* Wl1  = (const float*)d_in[10];
    const float* bl1  = (const float*)d_in[11];
    const float* Wr1  = (const float*)d_in[12];
    const float* br1  = (const float*)d_in[13];
    const float* We1  = (const float*)d_in[14];
    const float* att1 = (const float*)d_in[15];
    const float* bias1= (const float*)d_in[16];
    const float* Wmu  = (const float*)d_in[17];
    const float* bmu  = (const float*)d_in[18];

    const int E = in_sizes[1] / 2;
    const int n = in_sizes[0] / IND;
    const int* src = edge_index;
    const int* dst = edge_index + E;

    void *p_xl, *p_xr, *p_h1, *p_h2;
    cudaGetSymbolAddress(&p_xl, g_xl);
    cudaGetSymbolAddress(&p_xr, g_xr);
    cudaGetSymbolAddress(&p_h1, g_h1);
    cudaGetSymbolAddress(&p_h2, g_h2);

    cudaFuncSetAttribute(gemm_tf32_dual,
                         cudaFuncAttributeMaxDynamicSharedMemorySize,
                         GEMM_SMEM_BYTES);

    // Persistent side stream + fork/join events (host objects, created once;
    // graph capture records only the dependency structure).
    static cudaStream_t s2 = nullptr;
    static cudaEvent_t evFork = nullptr, evJoin = nullptr;
    if (s2 == nullptr) {
        cudaStreamCreateWithFlags(&s2, cudaStreamNonBlocking);
        cudaEventCreateWithFlags(&evFork, cudaEventDisableTiming);
        cudaEventCreateWithFlags(&evJoin, cudaEventDisableTiming);
    }

    int eb = (E + 255) / 256;
    int sb = (n + 1023) / 1024;

    dim3 gdual(4, (n + 127) / 128);
    int aggBlocks = (n * 32 + 255) / 256;

    // ---- fork: CSR chain on s2, layer-0 GEMM on the main stream ----
    cudaEventRecord(evFork, 0);
    cudaStreamWaitEvent(s2, evFork, 0);

    edge_accum_kernel<<<eb, 256, 0, s2>>>(dst, edge_attr, E);
    scan_block_kernel<<<sb, 1024, 0, s2>>>(n);
    scan_add2_kernel<<<sb, 1024, 0, s2>>>(n);
    scatter_kernel<<<eb, 256, 0, s2>>>(dst, src, edge_attr, E);
    cudaEventRecord(evJoin, s2);

    gemm_tf32_dual<<<gdual, 256, GEMM_SMEM_BYTES>>>(x, Wl0, Wr0, bl0, br0,
                                   (float*)p_xl, (float*)p_xr, n, IND);

    // ---- join: agg0 needs both the GEMM outputs and the CSR ----
    cudaStreamWaitEvent(0, evJoin, 0);

    gat_agg<<<aggBlocks, 256>>>((const float*)p_xl, (const float*)p_xr,
                                We0, att0, bias0, (float*)p_h1, n, 0);

    // ---- layer 1 ----
    gemm_tf32_dual<<<gdual, 256, GEMM_SMEM_BYTES>>>((const float*)p_h1, Wl1, Wr1, bl1, br1,
                                   (float*)p_xl, (float*)p_xr, n, CC);
    gat_agg<<<aggBlocks, 256>>>((const float*)p_xl, (const float*)p_xr,
                                We1, att1, bias1, (float*)p_h2, n, 1);   // clears g_loop

    // ---- final projection ----
    dim3 gmu((LAT + 63) / 64, (n + 63) / 64);
    sgemm_bias<<<gmu, 256>>>((const float*)p_h2, Wmu, bmu, (float*)d_out, n, CC, LAT);
}

// round 17
// speedup vs baseline: 1.0284x; 1.0284x over previous
#include <cuda_runtime.h>
#include <math.h>

#define NN 50000
#define EE 800000
#define IND 256
#define HH 4
#define CC 64
#define HC 256   // H*C
#define LAT 32
#define EDIM 3

typedef unsigned long long ull;

// ---------------- scratch (device globals; no allocation allowed) ----------------
// g_deg and g_loop are SELF-CLEANING across calls:
//   g_deg:  edge_accum raises 0->deg, scatter counts back down to 0.
//   g_loop: accumulated by edge_accum, scaled by scan_add2, zeroed by the
//           layer-1 gat_agg after its final read.
__device__ int    g_deg[NN];
__device__ int    g_off[NN + 1];
__device__ float4 g_erec[EE];       // {src_as_float, ea0, ea1, ea2} in CSR order
__device__ int    g_bsum[64];
__device__ float  g_loop[NN * EDIM];
__device__ float  g_xl[NN * HC];
__device__ float  g_xr[NN * HC];
__device__ float  g_h1[NN * CC];
__device__ float  g_h2[NN * CC];

// ---------------- packed f32x2 helpers ----------------
__device__ __forceinline__ ull pk2(float lo, float hi) {
    ull r; asm("mov.b64 %0, {%1,%2};" : "=l"(r) : "f"(lo), "f"(hi)); return r;
}
__device__ __forceinline__ ull bc2(float x) { return pk2(x, x); }
__device__ __forceinline__ ull fma2(ull a, ull b, ull c) {
    ull d; asm("fma.rn.f32x2 %0, %1, %2, %3;" : "=l"(d) : "l"(a), "l"(b), "l"(c)); return d;
}
__device__ __forceinline__ ull add2(ull a, ull b) {
    ull d; asm("add.rn.f32x2 %0, %1, %2;" : "=l"(d) : "l"(a), "l"(b)); return d;
}
__device__ __forceinline__ ull mul2(ull a, ull b) {
    ull d; asm("mul.rn.f32x2 %0, %1, %2;" : "=l"(d) : "l"(a), "l"(b)); return d;
}
__device__ __forceinline__ void unpk2(ull v, float& lo, float& hi) {
    asm("mov.b64 {%0,%1}, %2;" : "=f"(lo), "=f"(hi) : "l"(v));
}

// ---------------- CSR build ----------------
__global__ void edge_accum_kernel(const int* __restrict__ dst,
                                  const float* __restrict__ ea, int e) {
    int i = blockIdx.x * blockDim.x + threadIdx.x;
    if (i < e) {
        int d = dst[i];
        atomicAdd(&g_deg[d], 1);
        atomicAdd(&g_loop[d * 3 + 0], ea[i * 3 + 0]);
        atomicAdd(&g_loop[d * 3 + 1], ea[i * 3 + 1]);
        atomicAdd(&g_loop[d * 3 + 2], ea[i * 3 + 2]);
    }
}

__global__ void scan_block_kernel(int n) {
    __shared__ int tmp[1024];
    int tid = threadIdx.x;
    int i = blockIdx.x * 1024 + tid;
    int v = (i < n) ? g_deg[i] : 0;
    tmp[tid] = v;
    __syncthreads();
    for (int d = 1; d < 1024; d <<= 1) {
        int t = (tid >= d) ? tmp[tid - d] : 0;
        __syncthreads();
        tmp[tid] += t;
        __syncthreads();
    }
    if (i < n) g_off[i + 1] = tmp[tid];
    if (tid == 1023) g_bsum[blockIdx.x] = tmp[tid];
    if (i == 0) g_off[0] = 0;
}

// merged: block-prefix from g_bsum (computed in-kernel) + loop_attr mean.
// g_deg stays intact here; scatter consumes it as a countdown.
__global__ void scan_add2_kernel(int n) {
    __shared__ int pre;
    if (threadIdx.x == 0) {
        int s = 0;
        for (int b = 0; b < (int)blockIdx.x; b++) s += g_bsum[b];
        pre = s;
    }
    __syncthreads();
    int i = blockIdx.x * 1024 + threadIdx.x;
    if (i < n) {
        g_off[i + 1] += pre;
        float inv = 1.0f / (float)max(g_deg[i], 1);
        g_loop[i * 3 + 0] *= inv;
        g_loop[i * 3 + 1] *= inv;
        g_loop[i * 3 + 2] *= inv;
    }
}

// writes packed edge records {src, ea0, ea1, ea2} into CSR slots.
// Uses g_deg as a countdown counter; leaves g_deg == 0 (self-cleaning).
__global__ void scatter_kernel(const int* __restrict__ dst,
                               const int* __restrict__ src,
                               const float* __restrict__ ea, int e) {
    int i = blockIdx.x * blockDim.x + threadIdx.x;
    if (i < e) {
        int d = dst[i];
        int p = g_off[d] + atomicSub(&g_deg[d], 1) - 1;
        g_erec[p] = make_float4(__int_as_float(src[i]),
                                ea[i * 3 + 0], ea[i * 3 + 1], ea[i * 3 + 2]);
    }
}

// ---------------- TF32 tensor-core GEMM (R12 config: best measured) ----------
#define AS_STRIDE 36
#define BS_STRIDE 136
#define AS_STAGE (128 * AS_STRIDE)
#define BS_STAGE (32 * BS_STRIDE)
#define NSTAGE 3
#define GEMM_SMEM_BYTES ((NSTAGE * AS_STAGE + NSTAGE * BS_STAGE) * 4)

__device__ __forceinline__ void cp16(unsigned saddr, const float* g, unsigned srcsz) {
    asm volatile("cp.async.cg.shared.global [%0], [%1], 16, %2;"
                 :: "r"(saddr), "l"(g), "r"(srcsz));
}

__global__ __launch_bounds__(256) void gemm_tf32_dual(
    const float* __restrict__ A,
    const float* __restrict__ Bl, const float* __restrict__ Br,
    const float* __restrict__ bl, const float* __restrict__ br,
    float* __restrict__ Cl, float* __restrict__ Cr,
    int M, int K)
{
    extern __shared__ float sm[];
    float* Asm = sm;
    float* Bsm = sm + NSTAGE * AS_STAGE;

    const int tid  = threadIdx.x;
    const int lane = tid & 31;
    const int warp = tid >> 5;
    const int g = lane >> 2;
    const int q = lane & 3;

    const int m_warp = (warp & 1) * 64;
    const int n_warp = (warp >> 1) * 32;

    const int row0 = blockIdx.y * 128;
    const int col0 = blockIdx.x * 128;
    const int half = (col0 >= 256);
    const float* Bp = half ? Br : Bl;
    const float* biasp = half ? br : bl;
    float* Cp = half ? Cr : Cl;
    const int bcol0 = col0 - half * 256;

    const int ar = tid >> 1;
    const int brow = tid >> 3;
    const int bc4 = (tid & 7) * 4;

    const unsigned asm_base = (unsigned)__cvta_generic_to_shared(Asm);
    const unsigned bsm_base = (unsigned)__cvta_generic_to_shared(Bsm);

    float acc[4][4][4] = {};
    const int nk = K >> 5;

    auto load_stage = [&](int stg, int k0) {
        const int garow = row0 + ar;
        const int carow = (garow < M) ? garow : (M - 1);
        const unsigned asz = (garow < M) ? 16u : 0u;
        const float* gA = A + (long)carow * K + k0;
        unsigned sA = asm_base + (stg * AS_STAGE + ar * AS_STRIDE) * 4;
        int cbase = (tid & 1) * 16;
        cp16(sA + (cbase + 0) * 4, gA + cbase + 0, asz);
        cp16(sA + (cbase + 4) * 4, gA + cbase + 4, asz);
        cp16(sA + (cbase + 8) * 4, gA + cbase + 8, asz);
        cp16(sA + (cbase + 12) * 4, gA + cbase + 12, asz);
        const float* gB = Bp + (long)(k0 + brow) * 256 + bcol0 + bc4;
        unsigned sB = bsm_base + (stg * BS_STAGE + brow * BS_STRIDE + bc4) * 4;
        cp16(sB, gB, 16u);
        cp16(sB + 32 * 4, gB + 32, 16u);
        cp16(sB + 64 * 4, gB + 64, 16u);
        cp16(sB + 96 * 4, gB + 96, 16u);
    };

    load_stage(0, 0);
    asm volatile("cp.async.commit_group;");
    load_stage(1, 32);
    asm volatile("cp.async.commit_group;");

    int stg = 0;
    int stg2 = 2;
    for (int kt = 0; kt < nk; kt++) {
        if (kt == nk - 1)
            asm volatile("cp.async.wait_group 0;");
        else
            asm volatile("cp.async.wait_group 1;");
        __syncthreads();

        if (kt + 2 < nk) {
            load_stage(stg2, (kt + 2) * 32);
            asm volatile("cp.async.commit_group;");
        }

        const float* As = Asm + stg * AS_STAGE;
        const float* Bs = Bsm + stg * BS_STAGE;

        #pragma unroll
        for (int kk = 0; kk < 32; kk += 8) {
            unsigned a[4][4], b[4][2];
            #pragma unroll
            for (int i = 0; i < 4; i++) {
                int r = m_warp + i * 16 + g;
                a[i][0] = __float_as_uint(As[r * AS_STRIDE + kk + q]) + 0x1000u;
                a[i][1] = __float_as_uint(As[(r + 8) * AS_STRIDE + kk + q]) + 0x1000u;
                a[i][2] = __float_as_uint(As[r * AS_STRIDE + kk + q + 4]) + 0x1000u;
                a[i][3] = __float_as_uint(As[(r + 8) * AS_STRIDE + kk + q + 4]) + 0x1000u;
            }
            #pragma unroll
            for (int j = 0; j < 4; j++) {
                int c = n_warp + j * 8 + g;
                b[j][0] = __float_as_uint(Bs[(kk + q) * BS_STRIDE + c]) + 0x1000u;
                b[j][1] = __float_as_uint(Bs[(kk + q + 4) * BS_STRIDE + c]) + 0x1000u;
            }
            #pragma unroll
            for (int i = 0; i < 4; i++)
                #pragma unroll
                for (int j = 0; j < 4; j++) {
                    asm volatile(
                        "mma.sync.aligned.m16n8k8.row.col.f32.tf32.tf32.f32 "
                        "{%0,%1,%2,%3}, {%4,%5,%6,%7}, {%8,%9}, {%0,%1,%2,%3};"
                        : "+f"(acc[i][j][0]), "+f"(acc[i][j][1]),
                          "+f"(acc[i][j][2]), "+f"(acc[i][j][3])
                        : "r"(a[i][0]), "r"(a[i][1]), "r"(a[i][2]), "r"(a[i][3]),
                          "r"(b[j][0]), "r"(b[j][1]));
                }
        }
        stg = (stg == NSTAGE - 1) ? 0 : stg + 1;
        stg2 = (stg2 == NSTAGE - 1) ? 0 : stg2 + 1;
    }

    #pragma unroll
    for (int i = 0; i < 4; i++) {
        int r0 = row0 + m_warp + i * 16 + g;
        #pragma unroll
        for (int j = 0; j < 4; j++) {
            int cl = bcol0 + n_warp + j * 8 + 2 * q;
            float b0 = biasp[cl], b1 = biasp[cl + 1];
            if (r0 < M) {
                Cp[(long)r0 * 256 + cl]     = acc[i][j][0] + b0;
                Cp[(long)r0 * 256 + cl + 1] = acc[i][j][1] + b1;
            }
            if (r0 + 8 < M) {
                Cp[(long)(r0 + 8) * 256 + cl]     = acc[i][j][2] + b0;
                Cp[(long)(r0 + 8) * 256 + cl + 1] = acc[i][j][3] + b1;
            }
        }
    }
}

// ---------------- fp32 tiled SGEMM (final projection only) ----------------
__global__ void sgemm_bias(const float* __restrict__ A, const float* __restrict__ B,
                           const float* __restrict__ bias, float* __restrict__ C,
                           int M, int K, int Nc) {
    __shared__ float As[16][64];
    __shared__ float Bs[16][64 + 4];
    int tid = threadIdx.x;
    int tx = tid & 15, ty = tid >> 4;
    int row0 = blockIdx.y * 64, col0 = blockIdx.x * 64;
    float acc[4][4] = {};
    for (int k0 = 0; k0 < K; k0 += 16) {
        #pragma unroll
        for (int i = tid; i < 64 * 16; i += 256) {
            int m = i >> 4, k = i & 15;
            int r = row0 + m;
            As[k][m] = (r < M) ? A[(long)r * K + k0 + k] : 0.0f;
        }
        #pragma unroll
        for (int i = tid; i < 16 * 64; i += 256) {
            int k = i >> 6, c = i & 63;
            int cc = col0 + c;
            Bs[k][c] = (cc < Nc) ? B[(long)(k0 + k) * Nc + cc] : 0.0f;
        }
        __syncthreads();
        #pragma unroll
        for (int k = 0; k < 16; k++) {
            float a[4], b[4];
            #pragma unroll
            for (int i = 0; i < 4; i++) a[i] = As[k][ty * 4 + i];
            #pragma unroll
            for (int j = 0; j < 4; j++) b[j] = Bs[k][tx * 4 + j];
            #pragma unroll
            for (int i = 0; i < 4; i++)
                #pragma unroll
                for (int j = 0; j < 4; j++)
                    acc[i][j] += a[i] * b[j];
        }
        __syncthreads();
    }
    #pragma unroll
    for (int i = 0; i < 4; i++) {
        int r = row0 + ty * 4 + i;
        if (r >= M) continue;
        #pragma unroll
        for (int j = 0; j < 4; j++) {
            int c = col0 + tx * 4 + j;
            if (c < Nc) C[(long)r * Nc + c] = acc[i][j] + bias[c];
        }
    }
}

// ---------------- fused GATv2 attention + aggregation ----------------
#define ABSMASK 0x7FFFFFFF7FFFFFFFULL

__global__ __launch_bounds__(256) void gat_agg(
        const float* __restrict__ xl, const float* __restrict__ xr,
        const float* __restrict__ We, const float* __restrict__ att,
        const float* __restrict__ bias, float* __restrict__ out,
        int n, int clear_loop) {
    int warp = (blockIdx.x * blockDim.x + threadIdx.x) >> 5;
    int lane = threadIdx.x & 31;
    if (warp >= n) return;
    const int node = warp;
    const int base = ((lane >> 3) << 6) | ((lane & 7) << 3);
    const int b4 = base >> 2;

    ull we0[4], we1[4], we2[4], attv[4], xrv[4];
    {
        const float4* We4 = (const float4*)We;
        const float4* at4 = (const float4*)att;
        const float4* xr4 = (const float4*)(xr + (long)node * HC);
        *(float4*)&we0[0] = We4[b4];        *(float4*)&we0[2] = We4[b4 + 1];
        *(float4*)&we1[0] = We4[64 + b4];   *(float4*)&we1[2] = We4[64 + b4 + 1];
        *(float4*)&we2[0] = We4[128 + b4];  *(float4*)&we2[2] = We4[128 + b4 + 1];
        *(float4*)&attv[0] = at4[b4];       *(float4*)&attv[2] = at4[b4 + 1];
        *(float4*)&xrv[0] = xr4[b4];        *(float4*)&xrv[2] = xr4[b4 + 1];
    }
    const ull C06 = 0x3F19999A3F19999AULL;   // {0.6f, 0.6f}
    const ull C04 = 0x3ECCCCCD3ECCCCCDULL;   // {0.4f, 0.4f}

    const int o0 = g_off[node];
    const int deg = g_off[node + 1] - o0;

    auto fetch = [&](int pos, int& sn, float& e0, float& e1, float& e2) {
        if (pos < deg) {
            float4 rec = __ldg(&g_erec[o0 + pos]);
            sn = __float_as_int(rec.x);
            e0 = rec.y; e1 = rec.z; e2 = rec.w;
        } else { sn = node; e0 = 0.f; e1 = 0.f; e2 = 0.f; }
    };

    auto logit = [&](const ull* cx, float e0, float e1, float e2) -> float {
        ull ea0 = bc2(e0), ea1 = bc2(e1), ea2 = bc2(e2);
        ull p2 = 0;
        #pragma unroll
        for (int j = 0; j < 4; j++) {
            ull bse = fma2(ea2, we2[j], fma2(ea1, we1[j], fma2(ea0, we0[j], xrv[j])));
            ull t = add2(cx[j], bse);
            ull l = fma2(C04, t & ABSMASK, mul2(C06, t));
            p2 = fma2(l, attv[j], p2);
        }
        float lo, hi;
        unpk2(p2, lo, hi);
        float p = lo + hi;
        p += __shfl_xor_sync(0xffffffffu, p, 1);
        p += __shfl_xor_sync(0xffffffffu, p, 2);
        p += __shfl_xor_sync(0xffffffffu, p, 4);
        return p;
    };

    // ---- state A seeded with the self-loop, state B empty ----
    ull accA[4], accB[4];
    float mA, sA, mB = -1e30f, sB = 0.f;
    {
        ull xvS[4];
        const float4* xp = (const float4*)(xl + (long)node * HC);
        *(float4*)&xvS[0] = xp[b4];
        *(float4*)&xvS[2] = xp[b4 + 1];
        float l0 = g_loop[node * 3 + 0];
        float l1 = g_loop[node * 3 + 1];
        float l2 = g_loop[node * 3 + 2];
        if (clear_loop && lane == 0) {   // last consumer resets g_loop to 0
            g_loop[node * 3 + 0] = 0.f;
            g_loop[node * 3 + 1] = 0.f;
            g_loop[node * 3 + 2] = 0.f;
        }
        mA = logit(xvS, l0, l1, l2);
        sA = 1.f;
        #pragma unroll
        for (int j = 0; j < 4; j++) { accA[j] = xvS[j]; accB[j] = 0; }
    }

    // ---- meta queue: pair 0 (current) + pair 1 (next) ----
    int snA0, snB0, snA1, snB1;
    float a00, a01, a02, b00, b01, b02;
    float a10, a11, a12, b10, b11, b12;
    fetch(0, snA0, a00, a01, a02);
    fetch(1, snB0, b00, b01, b02);
    ull xvA[4], xvB[4];
    {
        const float4* xp = (const float4*)(xl + (long)snA0 * HC);
        *(float4*)&xvA[0] = xp[b4]; *(float4*)&xvA[2] = xp[b4 + 1];
    }
    {
        const float4* xp = (const float4*)(xl + (long)snB0 * HC);
        *(float4*)&xvB[0] = xp[b4]; *(float4*)&xvB[2] = xp[b4 + 1];
    }
    fetch(2, snA1, a10, a11, a12);
    fetch(3, snB1, b10, b11, b12);

    for (int i = 0; i < deg; i += 2) {
        ull cxA[4], cxB[4];
        #pragma unroll
        for (int j = 0; j < 4; j++) { cxA[j] = xvA[j]; cxB[j] = xvB[j]; }
        const float cA0 = a00, cA1 = a01, cA2 = a02;
        const float cB0 = b00, cB1 = b01, cB2 = b02;
        const bool vB = (i + 1 < deg);

        if (i + 2 < deg) {
            const float4* xp = (const float4*)(xl + (long)snA1 * HC);
            *(float4*)&xvA[0] = xp[b4]; *(float4*)&xvA[2] = xp[b4 + 1];
        }
        if (i + 3 < deg) {
            const float4* xp = (const float4*)(xl + (long)snB1 * HC);
            *(float4*)&xvB[0] = xp[b4]; *(float4*)&xvB[2] = xp[b4 + 1];
        }
        snA0 = snA1; a00 = a10; a01 = a11; a02 = a12;
        snB0 = snB1; b00 = b10; b01 = b11; b02 = b12;
        fetch(i + 4, snA1, a10, a11, a12);
        fetch(i + 5, snB1, b10, b11, b12);

        float pA = logit(cxA, cA0, cA1, cA2);
        float pB = logit(cxB, cB0, cB1, cB2);
        if (!vB) pB = -1e30f;

        float nmA = fmaxf(mA, pA), nmB = fmaxf(mB, pB);
        float scA = __expf(mA - nmA), wA = __expf(pA - nmA);
        float scB = __expf(mB - nmB), wB = __expf(pB - nmB);
        if (!vB) wB = 0.f;
        sA = sA * scA + wA; mA = nmA;
        sB = sB * scB + wB; mB = nmB;
        ull scA2 = bc2(scA), wA2 = bc2(wA);
        ull scB2 = bc2(scB), wB2 = bc2(wB);
        #pragma unroll
        for (int j = 0; j < 4; j++) {
            accA[j] = fma2(wA2, cxA[j], mul2(accA[j], scA2));
            accB[j] = fma2(wB2, cxB[j], mul2(accB[j], scB2));
        }
    }

    // ---- merge states, head mean, bias, relu ----
    float nm = fmaxf(mA, mB);
    float fA = __expf(mA - nm), fB = __expf(mB - nm);
    float inv = 1.f / (sA * fA + sB * fB);
    ull fA2 = bc2(fA * inv), fB2 = bc2(fB * inv);
    float r[8];
    #pragma unroll
    for (int j = 0; j < 4; j++) {
        ull v2 = add2(mul2(accA[j], fA2), mul2(accB[j], fB2));
        float lo, hi;
        unpk2(v2, lo, hi);
        lo += __shfl_xor_sync(0xffffffffu, lo, 8);
        hi += __shfl_xor_sync(0xffffffffu, hi, 8);
        lo += __shfl_xor_sync(0xffffffffu, lo, 16);
        hi += __shfl_xor_sync(0xffffffffu, hi, 16);
        r[2 * j] = lo; r[2 * j + 1] = hi;
    }
    if (lane < 8) {
        float o[8];
        #pragma unroll
        for (int j = 0; j < 8; j++)
            o[j] = fmaxf(0.25f * r[j] + bias[base + j], 0.f);
        float4* op = (float4*)(out + (long)node * CC + base);
        op[0] = make_float4(o[0], o[1], o[2], o[3]);
        op[1] = make_float4(o[4], o[5], o[6], o[7]);
    }
}

// ---------------- launch ----------------
extern "C" void kernel_launch(void* const* d_in, const int* in_sizes, int n_in,
                              void* d_out, int out_size) {
    const float* x          = (const float*)d_in[0];
    const int*   edge_index = (const int*)d_in[1];
    const float* edge_attr  = (const float*)d_in[2];
    const float* Wl0  = (const float*)d_in[3];
    const float* bl0  = (const float*)d_in[4];
    const float* Wr0  = (const float*)d_in[5];
    const float* br0  = (const float*)d_in[6];
    const float* We0  = (const float*)d_in[7];
    const float* att0 = (const float*)d_in[8];
    const float* bias0= (const float*)d_in[9];
    const float* Wl1  = (const float*)d_in[10];
    const float* bl1  = (const float*)d_in[11];
    const float* Wr1  = (const float*)d_in[12];
    const float* br1  = (const float*)d_in[13];
    const float* We1  = (const float*)d_in[14];
    const float* att1 = (const float*)d_in[15];
    const float* bias1= (const float*)d_in[16];
    const float* Wmu  = (const float*)d_in[17];
    const float* bmu  = (const float*)d_in[18];

    const int E = in_sizes[1] / 2;
    const int n = in_sizes[0] / IND;
    const int* src = edge_index;
    const int* dst = edge_index + E;

    void *p_xl, *p_xr, *p_h1, *p_h2;
    cudaGetSymbolAddress(&p_xl, g_xl);
    cudaGetSymbolAddress(&p_xr, g_xr);
    cudaGetSymbolAddress(&p_h1, g_h1);
    cudaGetSymbolAddress(&p_h2, g_h2);

    cudaFuncSetAttribute(gemm_tf32_dual,
                         cudaFuncAttributeMaxDynamicSharedMemorySize,
                         GEMM_SMEM_BYTES);

    // Persistent side stream + fork/join events (host objects, created once;
    // graph capture records only the dependency structure).
    static cudaStream_t s2 = nullptr;
    static cudaEvent_t evFork = nullptr, evJoin = nullptr;
    if (s2 == nullptr) {
        cudaStreamCreateWithFlags(&s2, cudaStreamNonBlocking);
        cudaEventCreateWithFlags(&evFork, cudaEventDisableTiming);
        cudaEventCreateWithFlags(&evJoin, cudaEventDisableTiming);
    }

    int eb = (E + 255) / 256;
    int sb = (n + 1023) / 1024;

    dim3 gdual(4, (n + 127) / 128);
    int aggBlocks = (n * 32 + 255) / 256;

    // ---- fork: CSR chain on s2, layer-0 GEMM on the main stream ----
    cudaEventRecord(evFork, 0);
    cudaStreamWaitEvent(s2, evFork, 0);

    edge_accum_kernel<<<eb, 256, 0, s2>>>(dst, edge_attr, E);
    scan_block_kernel<<<sb, 1024, 0, s2>>>(n);
    scan_add2_kernel<<<sb, 1024, 0, s2>>>(n);
    scatter_kernel<<<eb, 256, 0, s2>>>(dst, src, edge_attr, E);
    cudaEventRecord(evJoin, s2);

    gemm_tf32_dual<<<gdual, 256, GEMM_SMEM_BYTES>>>(x, Wl0, Wr0, bl0, br0,
                                   (float*)p_xl, (float*)p_xr, n, IND);

    // ---- join: agg0 needs both the GEMM outputs and the CSR ----
    cudaStreamWaitEvent(0, evJoin, 0);

    gat_agg<<<aggBlocks, 256>>>((const float*)p_xl, (const float*)p_xr,
                                We0, att0, bias0, (float*)p_h1, n, 0);

    // ---- layer 1 ----
    gemm_tf32_dual<<<gdual, 256, GEMM_SMEM_BYTES>>>((const float*)p_h1, Wl1, Wr1, bl1, br1,
                                   (float*)p_xl, (float*)p_xr, n, CC);
    gat_agg<<<aggBlocks, 256>>>((const float*)p_xl, (const float*)p_xr,
                                We1, att1, bias1, (float*)p_h2, n, 1);   // clears g_loop

    // ---- final projection ----
    dim3 gmu((LAT + 63) / 64, (n + 63) / 64);
    sgemm_bias<<<gmu, 256>>>((const float*)p_h2, Wmu, bmu, (float*)d_out, n, CC, LAT);
}